// round 11
// baseline (speedup 1.0000x reference)
#include <cuda_runtime.h>
#include <cuda_bf16.h>

// Dims: B=64, T=64, D=32, H=128, W=256, L=64, K_SUB=2
typedef unsigned uint;

// ---------------- device scratch ----------------
__device__ float4 g_wihq[ 9 * 384];            // GRU input weights fp32 packed
__device__ float4 g_whhq[32 * 384];            // GRU hidden weights fp32 packed
// MLP weight tiles for ldmatrix: 16x16 bf16 tiles, row stride 48B (24 ushorts, 16 used)
__device__ unsigned short g_w0t[144 * 384];    // (256,144): 16 m-tiles x 9 k-tiles
__device__ unsigned short g_w2t[128 * 384];    // (128,256): 8 m-tiles x 16 k-tiles
// w1 A-fragments, per-thread: 16 k-tiles x 4 regs
__device__ uint4 g_w1f[512 * 16];

// RK coefficient tables (row s: coeffs for k0..k5; stage s uses k0..ks)
__constant__ float c_AT[6][6] = {
    {0.161f, 0, 0, 0, 0, 0},
    {(float)-0.008480655492356989, (float)0.335480655492357, 0, 0, 0, 0},
    {(float)2.8971530571054935, (float)-6.359448489975075, (float)4.3622954328695815, 0, 0, 0},
    {(float)5.325864828439257, (float)-11.748883564062828, (float)7.4955393428898365,
     (float)-0.09249506636175525, 0, 0},
    {(float)5.86145544294642, (float)-12.92096931784711, (float)8.159367898576159,
     (float)-0.071584973281401, (float)-0.028269050394068383, 0},
    {(float)0.09646076681806523, 0.01f, (float)0.4798896504144996,
     (float)1.379008574103742, (float)-3.290069515436081, (float)2.324710524099774}};
__constant__ float c_CC[5] = {0.161f, 0.327f, 0.9f, (float)0.9800255409045097, 1.0f};

__device__ __forceinline__ uint pk_bf2(float a, float b) {
    uint lo = (uint)__bfloat16_as_ushort(__float2bfloat16_rn(a));
    uint hi = (uint)__bfloat16_as_ushort(__float2bfloat16_rn(b));
    return (hi << 16) | lo;
}

__global__ void prep_kernel(const float* __restrict__ w0, const float* __restrict__ w1,
                            const float* __restrict__ w2, const float* __restrict__ wih,
                            const float* __restrict__ whh)
{
    int i0 = blockIdx.x * blockDim.x + threadIdx.x;
    int stride = gridDim.x * blockDim.x;

    // w0 tiles: tile = mt*9+kt; element (r,c) at tile*384 + r*24 + c (c<16 valid)
    // K index 0 -> col0 (t_hi), 1..128 -> h, 129 -> col0 again (t_lo), else 0
    for (int idx = i0; idx < 144 * 384; idx += stride) {
        int tile = idx / 384, e = idx % 384, r = e / 24, c = e % 24;
        float v = 0.f;
        if (c < 16) {
            int mt = tile / 9, kt = tile % 9;
            int R = 16 * mt + r, K = 16 * kt + c;
            if (K < 129)       v = w0[R * 129 + K];
            else if (K == 129) v = w0[R * 129];
        }
        g_w0t[idx] = __bfloat16_as_ushort(__float2bfloat16_rn(v));
    }
    // w2 tiles: tile = mt*16+kt
    for (int idx = i0; idx < 128 * 384; idx += stride) {
        int tile = idx / 384, e = idx % 384, r = e / 24, c = e % 24;
        float v = 0.f;
        if (c < 16) {
            int mt = tile >> 4, kt = tile & 15;
            int R = 16 * mt + r, K = 16 * kt + c;
            v = w2[R * 256 + K];
        }
        g_w2t[idx] = __bfloat16_as_ushort(__float2bfloat16_rn(v));
    }
    // w1 fragments: idx = t*64 + kt*4 + i
    for (int idx = i0; idx < 512 * 64; idx += stride) {
        int t = idx >> 6, rem = idx & 63, kt = rem >> 2, i = rem & 3;
        int wid = t >> 5, lane = t & 31, g = lane >> 2, tig = lane & 3;
        int R = 16 * wid + g + ((i & 1) ? 8 : 0);
        int K = 16 * kt + 2 * tig + ((i & 2) ? 8 : 0);
        ((uint*)g_w1f)[idx] = pk_bf2(w1[R * 256 + K], w1[R * 256 + K + 1]);
    }
    // GRU fp32 packs
    for (int idx = i0; idx < 9 * 384; idx += stride) {
        int k4 = idx / 384, j = idx % 384, k = 4 * k4;
        float4 v;
        v.x = (k + 0 < 33) ? wih[j * 33 + k + 0] : 0.f;
        v.y = (k + 1 < 33) ? wih[j * 33 + k + 1] : 0.f;
        v.z = (k + 2 < 33) ? wih[j * 33 + k + 2] : 0.f;
        v.w = (k + 3 < 33) ? wih[j * 33 + k + 3] : 0.f;
        g_wihq[idx] = v;
    }
    for (int idx = i0; idx < 32 * 384; idx += stride) {
        int k4 = idx / 384, j = idx % 384, k = 4 * k4;
        g_whhq[idx] = make_float4(whh[j * 128 + k], whh[j * 128 + k + 1],
                                  whh[j * 128 + k + 2], whh[j * 128 + k + 3]);
    }
}

// ---------------- helpers ----------------
__device__ __forceinline__ uint smem_u32(const void* p) {
    return (uint)__cvta_generic_to_shared(p);
}
__device__ __forceinline__ void ldsm4(uint& r0, uint& r1, uint& r2, uint& r3, uint addr) {
    asm volatile("ldmatrix.sync.aligned.m8n8.x4.shared.b16 {%0,%1,%2,%3}, [%4];"
                 : "=r"(r0), "=r"(r1), "=r"(r2), "=r"(r3) : "r"(addr));
}
__device__ __forceinline__ void mma16816(float* d,
                                         uint a0, uint a1, uint a2, uint a3,
                                         uint b0, uint b1) {
    asm volatile("mma.sync.aligned.m16n8k16.row.col.f32.bf16.bf16.f32 "
                 "{%0,%1,%2,%3}, {%4,%5,%6,%7}, {%8,%9}, {%0,%1,%2,%3};"
                 : "+f"(d[0]), "+f"(d[1]), "+f"(d[2]), "+f"(d[3])
                 : "r"(a0), "r"(a1), "r"(a2), "r"(a3), "r"(b0), "r"(b1));
}
__device__ __forceinline__ float tanh_fast(float x) {
    float y; asm("tanh.approx.f32 %0, %1;" : "=f"(y) : "f"(x)); return y;
}
__device__ __forceinline__ float softplus_fast(float x) {
    return fmaxf(x, 0.f) + __logf(1.f + __expf(-fabsf(x)));
}
__device__ __forceinline__ float sigmoid_fast(float x) { return 1.f / (1.f + __expf(-x)); }
__device__ __forceinline__ float sigmoidp(float x) { return 1.f / (1.f + expf(-x)); }
__device__ __forceinline__ unsigned short bf16u(float v) {
    return __bfloat16_as_ushort(__float2bfloat16_rn(v));
}
__device__ __forceinline__ float bf2f(unsigned short u) {
    return __uint_as_float(((uint)u) << 16);
}

// dynamic smem: phase 1 = whh fp32 (196608B); phase 2 = w0 tiles (110592B) + w2 tiles (98304B)
#define DYN_SMEM_BYTES 208896
#define W2_SMEM_OFF    110592

__global__ void __launch_bounds__(512, 1)
solve_kernel(const float* __restrict__ ts, const float* __restrict__ ys,
             const float* __restrict__ scale,
             const float* __restrict__ mlp_b0, const float* __restrict__ mlp_b1,
             const float* __restrict__ mlp_b2,
             const float* __restrict__ gru_b, const float* __restrict__ gru_bn,
             const float* __restrict__ htl_w, const float* __restrict__ htl_b,
             const float* __restrict__ htb_w, const float* __restrict__ htb_b,
             const float* __restrict__ lti_w, const float* __restrict__ lti_b,
             const float* __restrict__ lth_w, const float* __restrict__ lth_b,
             float* __restrict__ out)
{
    const int b   = blockIdx.x;
    const int tid = threadIdx.x;
    const int lane = tid & 31, wid = tid >> 5;
    const int g = lane >> 2, tig = lane & 3;

    extern __shared__ __align__(16) char s_dyn[];

    __shared__ __align__(16) float s_xg[36];
    __shared__ __align__(16) float s_hid[128];
    __shared__ float s_ih[384], s_hh[384];
    __shared__ __align__(16) float s_y[136];
    __shared__ float s_k[5][136];                        // k-stage history
    __shared__ __align__(4) unsigned short s_xb[144];    // bf16 [t_hi, h(128), t_lo, 0..]
    __shared__ __align__(4) unsigned short s_a0b[256];
    __shared__ __align__(4) unsigned short s_a1b[256];
    __shared__ float s_z0[64];
    __shared__ float s_beta;

    const int OFF_H = 64 * 64 * 5;
    const int OFF_Z = OFF_H + 64 * 64 * 128;

    // ---- phase 1: whh into smem ----
    float4* s_whh = (float4*)s_dyn;
    for (int i = tid; i < 32 * 384; i += 512) s_whh[i] = g_whhq[i];

    const float gb  = (tid < 384) ? gru_b[tid]  : 0.f;
    const float gbn = (tid < 128) ? gru_bn[tid] : 0.f;

    if (tid < 128) s_hid[tid] = 0.f;
    if (tid >= 33 && tid < 36) s_xg[tid] = 0.f;
    __syncthreads();

    // ---------------- GRU over reversed sequence ----------------
    for (int step = 0; step < 64; ++step) {
        int r = 63 - step;
        if (tid == 0) s_xg[0] = ts[b * 64 + r];
        if (tid >= 1 && tid < 33) s_xg[tid] = ys[(b * 64 + r) * 32 + (tid - 1)];
        __syncthreads();

        if (tid < 384) {
            const float4* xg4 = (const float4*)s_xg;
            const float4* h4  = (const float4*)s_hid;
            int row = tid;
            float a0 = gb, a1 = 0.f;
            #pragma unroll
            for (int k = 0; k < 9; ++k) {
                float4 w = g_wihq[k * 384 + row];
                float4 x = xg4[k];
                a0 = fmaf(w.x, x.x, fmaf(w.z, x.z, a0));
                a1 = fmaf(w.y, x.y, fmaf(w.w, x.w, a1));
            }
            float c0 = 0.f, c1 = 0.f;
            #pragma unroll 8
            for (int k = 0; k < 32; ++k) {
                float4 w = s_whh[k * 384 + row];
                float4 x = h4[k];
                c0 = fmaf(w.x, x.x, fmaf(w.z, x.z, c0));
                c1 = fmaf(w.y, x.y, fmaf(w.w, x.w, c1));
            }
            s_ih[row] = a0 + a1;
            s_hh[row] = c0 + c1;
        }
        __syncthreads();
        if (tid < 128) {
            float rr = sigmoidp(s_ih[tid] + s_hh[tid]);
            float zz = sigmoidp(s_ih[128 + tid] + s_hh[128 + tid]);
            float nn = tanhf(s_ih[256 + tid] + rr * (s_hh[256 + tid] + gbn));
            s_hid[tid] = nn + zz * (s_hid[tid] - nn);
        }
        __syncthreads();
    }

    // ---------------- head ----------------
    if (tid < 64) {
        float acc = htl_b[tid];
        #pragma unroll 8
        for (int k = 0; k < 128; ++k) acc = fmaf(htl_w[tid * 128 + k], s_hid[k], acc);
        s_z0[tid] = acc;
        out[OFF_Z + b * 64 + tid] = acc;
    }
    __syncthreads();
    if (tid < 128) {
        float acc = lth_b[tid];
        #pragma unroll 8
        for (int k = 0; k < 64; ++k) acc = fmaf(lth_w[tid * 64 + k], s_z0[k], acc);
        s_y[5 + tid] = acc;
    }
    if (tid == 0) {
        float lg[5], mx = -1e30f;
        #pragma unroll
        for (int m = 0; m < 5; ++m) {
            float acc = lti_b[m];
            for (int k = 0; k < 64; ++k) acc = fmaf(lti_w[m * 64 + k], s_z0[k], acc);
            lg[m] = acc; mx = fmaxf(mx, acc);
        }
        float sum = 0.f;
        #pragma unroll
        for (int m = 0; m < 5; ++m) { float t = expf(lg[m] - mx); s_y[m] = t; sum += t; }
        #pragma unroll
        for (int m = 0; m < 5; ++m) s_y[m] /= sum;
    }
    __syncthreads();   // done with s_whh; s_y ready

    // ---- phase 2: MLP weight tiles into smem ----
    {
        uint4* dst0 = (uint4*)s_dyn;
        const uint4* src0 = (const uint4*)g_w0t;
        for (int i = tid; i < 144 * 384 / 8; i += 512) dst0[i] = src0[i];
        uint4* dst2 = (uint4*)(s_dyn + W2_SMEM_OFF);
        const uint4* src2 = (const uint4*)g_w2t;
        for (int i = tid; i < 128 * 384 / 8; i += 512) dst2[i] = src2[i];
    }

    // w1 fragments into registers
    uint4 w1f[16];
    #pragma unroll
    for (int j = 0; j < 16; ++j) w1f[j] = g_w1f[tid * 16 + j];

    // per-thread constants
    const int rowg = 16 * wid + g;
    const float b0lo = mlp_b0[rowg], b0hi = mlp_b0[rowg + 8];
    const float b1lo = mlp_b1[rowg], b1hi = mlp_b1[rowg + 8];
    float b2lo = 0.f, b2hi = 0.f;
    if (wid < 8) { b2lo = mlp_b2[rowg]; b2hi = mlp_b2[rowg + 8]; }
    const float scl = scale[0];

    float hw0 = 0.f, hw1 = 0.f, hw2 = 0.f, hw3 = 0.f, htbb = 0.f;
    if (wid == 15) {
        hw0 = htb_w[lane]; hw1 = htb_w[lane + 32];
        hw2 = htb_w[lane + 64]; hw3 = htb_w[lane + 96];
        htbb = htb_b[0];
    }

    const uint laneoff = (uint)((lane & 15) * 48 + (lane >> 4) * 16);
    const uint w0base = smem_u32(s_dyn) + (uint)(wid * 9 * 768) + laneoff;
    const uint w2base = smem_u32(s_dyn) + W2_SMEM_OFF + (uint)(wid * 16 * 768) + laneoff;

    // init s_xb from initial state; t=0; y-base registers
    if (tid < 128) s_xb[1 + tid] = bf16u(s_y[5 + tid]);
    if (tid == 256) { s_xb[0] = 0; s_xb[129] = 0; }
    if (tid >= 130 && tid < 144) s_xb[tid] = 0;
    float ya = 0.f, yb = 0.f;
    if (wid < 8 && tig == 0) { ya = s_y[5 + rowg]; yb = s_y[13 + rowg]; }
    // SEIAR base + stage state in warp 15 lane 0 registers
    float yS0 = 0, yS1 = 0, yS2 = 0, yS3 = 0, yS4 = 0;   // y-base
    float tS0 = 0, tS1 = 0, tS2 = 0, tS3 = 0, tS4 = 0;   // stage state
    if (wid == 15 && lane == 0) {
        yS0 = s_y[0]; yS1 = s_y[1]; yS2 = s_y[2]; yS3 = s_y[3]; yS4 = s_y[4];
        tS0 = yS0; tS1 = yS1; tS2 = yS2; tS3 = yS3; tS4 = yS4;
    }
    __syncthreads();

    // ---------------- tsit5: 6 stages, 3 barriers each ----------------
    auto tsit5 = [&](float tt, float h, float t_after) {
        #pragma unroll 1
        for (int s = 0; s < 6; ++s) {
            // --- phase A: layer 0 (+ beta on warp 15); 4 acc sets (chain 3) ---
            {
                const uint* x32 = (const uint*)s_xb;
                float ac[4][4] = {};
                #pragma unroll
                for (int kt = 0; kt < 9; ++kt) {
                    uint a0, a1, a2, a3;
                    ldsm4(a0, a1, a2, a3, w0base + (uint)(kt * 768));
                    uint p0 = 0, p1 = 0;
                    if (lane < 4) { p0 = x32[8 * kt + lane]; p1 = x32[8 * kt + 4 + lane]; }
                    mma16816(ac[kt & 3], a0, a1, a2, a3, p0, p1);
                }
                if (wid == 15) {
                    float p = fmaf(hw0, bf2f(s_xb[1 + lane]),
                              fmaf(hw1, bf2f(s_xb[33 + lane]),
                              fmaf(hw2, bf2f(s_xb[65 + lane]),
                                   hw3 * bf2f(s_xb[97 + lane]))));
                    #pragma unroll
                    for (int o = 16; o > 0; o >>= 1) p += __shfl_xor_sync(0xffffffffu, p, o);
                    if (lane == 0) s_beta = sigmoid_fast(0.01f * (p + htbb));
                }
                if (tig == 0) {
                    float d0 = (ac[0][0] + ac[1][0]) + (ac[2][0] + ac[3][0]);
                    float d2 = (ac[0][2] + ac[1][2]) + (ac[2][2] + ac[3][2]);
                    s_a0b[rowg]     = bf16u(softplus_fast(d0 + b0lo));
                    s_a0b[rowg + 8] = bf16u(softplus_fast(d2 + b0hi));
                }
            }
            __syncthreads();

            // --- phase B: layer 1 (A fragments in registers); 4 acc sets (chain 4) ---
            {
                const uint* y32 = (const uint*)s_a0b;
                float ac[4][4] = {};
                #pragma unroll
                for (int kt = 0; kt < 16; ++kt) {
                    uint p0 = 0, p1 = 0;
                    if (lane < 4) { p0 = y32[8 * kt + lane]; p1 = y32[8 * kt + 4 + lane]; }
                    mma16816(ac[kt & 3], w1f[kt].x, w1f[kt].y, w1f[kt].z, w1f[kt].w, p0, p1);
                }
                if (tig == 0) {
                    float d0 = (ac[0][0] + ac[1][0]) + (ac[2][0] + ac[3][0]);
                    float d2 = (ac[0][2] + ac[1][2]) + (ac[2][2] + ac[3][2]);
                    s_a1b[rowg]     = bf16u(softplus_fast(d0 + b1lo));
                    s_a1b[rowg + 8] = bf16u(softplus_fast(d2 + b1hi));
                }
            }
            __syncthreads();

            // --- phase C: layer 2 (full-K, warps 0-7, 4 acc sets) fused with RK combine ---
            if (wid < 8) {
                const uint* y32 = (const uint*)s_a1b;
                float ac[4][4] = {};
                #pragma unroll
                for (int kt = 0; kt < 16; ++kt) {
                    uint a0, a1, a2, a3;
                    ldsm4(a0, a1, a2, a3, w2base + (uint)(kt * 768));
                    uint p0 = 0, p1 = 0;
                    if (lane < 4) { p0 = y32[8 * kt + lane]; p1 = y32[8 * kt + 4 + lane]; }
                    mma16816(ac[kt & 3], a0, a1, a2, a3, p0, p1);
                }
                if (tig == 0) {
                    float d0 = (ac[0][0] + ac[1][0]) + (ac[2][0] + ac[3][0]);
                    float d2 = (ac[0][2] + ac[1][2]) + (ac[2][2] + ac[3][2]);
                    float kA = scl * (0.1f * tanh_fast(1e-4f * (d0 + b2lo)));
                    float kB = scl * (0.1f * tanh_fast(1e-4f * (d2 + b2hi)));
                    float sA = c_AT[s][s] * kA, sB = c_AT[s][s] * kB;
                    #pragma unroll 1
                    for (int j = 0; j < s; ++j) {
                        sA += c_AT[s][j] * s_k[j][5 + rowg];
                        sB += c_AT[s][j] * s_k[j][13 + rowg];
                    }
                    if (s < 5) { s_k[s][5 + rowg] = kA; s_k[s][13 + rowg] = kB; }
                    float vA = ya + h * sA, vB = yb + h * sB;
                    s_xb[1 + rowg] = bf16u(vA);
                    s_xb[9 + rowg] = bf16u(vB);
                    if (s == 5) { ya = vA; yb = vB; s_y[5 + rowg] = vA; s_y[13 + rowg] = vB; }
                }
            } else if (wid == 15 && lane == 0) {
                // SEIAR: all 5 components serially in one lane (no warp coupling)
                float S = tS0, E = tS1, I = tS2, A_ = tS3;
                float LL = 0.5f * I + A_;
                float bSL = s_beta * S * LL;
                float k0v = -bSL;
                float k1v = bSL - 0.526f * E;
                float k2v = fmaf((float)(0.667 * 0.526), E, -(0.244f * I));
                float k3v = fmaf((float)((1.0 - 0.667) * 0.526), E, -(0.244f * A_));
                float k4v = fmaf((float)(0.98 * 0.244), I, 0.244f * A_);
                float s0 = c_AT[s][s] * k0v, s1 = c_AT[s][s] * k1v, s2 = c_AT[s][s] * k2v;
                float s3 = c_AT[s][s] * k3v, s4 = c_AT[s][s] * k4v;
                #pragma unroll 1
                for (int j = 0; j < s; ++j) {
                    float c = c_AT[s][j];
                    s0 += c * s_k[j][0]; s1 += c * s_k[j][1]; s2 += c * s_k[j][2];
                    s3 += c * s_k[j][3]; s4 += c * s_k[j][4];
                }
                if (s < 5) {
                    s_k[s][0] = k0v; s_k[s][1] = k1v; s_k[s][2] = k2v;
                    s_k[s][3] = k3v; s_k[s][4] = k4v;
                }
                tS0 = yS0 + h * s0; tS1 = yS1 + h * s1; tS2 = yS2 + h * s2;
                tS3 = yS3 + h * s3; tS4 = yS4 + h * s4;
                if (s == 5) {
                    yS0 = tS0; yS1 = tS1; yS2 = tS2; yS3 = tS3; yS4 = tS4;
                    s_y[0] = tS0; s_y[1] = tS1; s_y[2] = tS2; s_y[3] = tS3; s_y[4] = tS4;
                }
                // t-slot for next vf eval
                float tn = (s < 5) ? tt + c_CC[s] * h : t_after;
                unsigned short u = bf16u(tn);
                s_xb[0] = u;
                s_xb[129] = bf16u(tn - bf2f(u));
            }
            __syncthreads();
        }
    };

    float t0v = 0.f;
    for (int st = 0; st < 64; ++st) {
        float tn = ts[b * 64 + st];
        float dt = (tn - t0v) * 0.5f;    // K_SUB = 2
        tsit5(t0v,      dt, t0v + dt);
        tsit5(t0v + dt, dt, tn);
        t0v = tn;
        if (tid < 5)   out[(b * 64 + st) * 5 + tid] = s_y[tid];
        if (tid < 128) out[OFF_H + (b * 64 + st) * 128 + tid] = s_y[5 + tid];
    }
}

extern "C" void kernel_launch(void* const* d_in, const int* in_sizes, int n_in,
                              void* d_out, int out_size) {
    const float* ts      = (const float*)d_in[0];
    const float* ys      = (const float*)d_in[1];
    const float* scale   = (const float*)d_in[2];
    const float* mlp_w0  = (const float*)d_in[3];
    const float* mlp_b0  = (const float*)d_in[4];
    const float* mlp_w1  = (const float*)d_in[5];
    const float* mlp_b1  = (const float*)d_in[6];
    const float* mlp_w2  = (const float*)d_in[7];
    const float* mlp_b2  = (const float*)d_in[8];
    const float* gru_wih = (const float*)d_in[9];
    const float* gru_whh = (const float*)d_in[10];
    const float* gru_b   = (const float*)d_in[11];
    const float* gru_bn  = (const float*)d_in[12];
    const float* htl_w   = (const float*)d_in[13];
    const float* htl_b   = (const float*)d_in[14];
    const float* htb_w   = (const float*)d_in[15];
    const float* htb_b   = (const float*)d_in[16];
    const float* lti_w   = (const float*)d_in[17];
    const float* lti_b   = (const float*)d_in[18];
    const float* lth_w   = (const float*)d_in[19];
    const float* lth_b   = (const float*)d_in[20];

    static int attr_set = 0;
    if (!attr_set) {
        cudaFuncSetAttribute(solve_kernel,
                             cudaFuncAttributeMaxDynamicSharedMemorySize,
                             DYN_SMEM_BYTES);
        attr_set = 1;
    }

    prep_kernel<<<96, 256>>>(mlp_w0, mlp_w1, mlp_w2, gru_wih, gru_whh);
    solve_kernel<<<64, 512, DYN_SMEM_BYTES>>>(ts, ys, scale, mlp_b0, mlp_b1, mlp_b2,
                              gru_b, gru_bn, htl_w, htl_b, htb_w, htb_b,
                              lti_w, lti_b, lth_w, lth_b, (float*)d_out);
}

// round 12
// speedup vs baseline: 1.2892x; 1.2892x over previous
#include <cuda_runtime.h>
#include <cuda_bf16.h>

// Dims: B=64, T=64, D=32, H=128, W=256, L=64, K_SUB=2
typedef unsigned uint;

// ---------------- device scratch ----------------
__device__ float4 g_wihq[ 9 * 384];            // GRU input weights fp32 packed
__device__ float4 g_whhq[32 * 384];            // GRU hidden weights fp32 packed
// MLP weight tiles for ldmatrix: 16x16 bf16 tiles, row stride 48B (24 ushorts, 16 used)
__device__ unsigned short g_w0t[144 * 384];    // (256,144): 16 m-tiles x 9 k-tiles
__device__ unsigned short g_w2t[128 * 384];    // (128,256): 8 m-tiles x 16 k-tiles
// w1 A-fragments, per-thread: 16 k-tiles x 4 regs
__device__ uint4 g_w1f[512 * 16];

// Butcher table split: diagonal (current-k) coeff + zero-padded off-diagonal rows.
// stage s: y_next = y + h*(c_DIAG[s]*k_s + sum_{j=0..4} c_OFF[s][j]*k_j)
__constant__ float c_DIAG[6] = {
    0.161f, (float)0.335480655492357, (float)4.3622954328695815,
    (float)-0.09249506636175525, (float)-0.028269050394068383,
    (float)2.324710524099774};
__constant__ float c_OFF[6][5] = {
    {0, 0, 0, 0, 0},
    {(float)-0.008480655492356989, 0, 0, 0, 0},
    {(float)2.8971530571054935, (float)-6.359448489975075, 0, 0, 0},
    {(float)5.325864828439257, (float)-11.748883564062828, (float)7.4955393428898365, 0, 0},
    {(float)5.86145544294642, (float)-12.92096931784711, (float)8.159367898576159,
     (float)-0.071584973281401, 0},
    {(float)0.09646076681806523, 0.01f, (float)0.4798896504144996,
     (float)1.379008574103742, (float)-3.290069515436081}};
__constant__ float c_CC[5] = {0.161f, 0.327f, 0.9f, (float)0.9800255409045097, 1.0f};

__device__ __forceinline__ uint pk_bf2(float a, float b) {
    uint lo = (uint)__bfloat16_as_ushort(__float2bfloat16_rn(a));
    uint hi = (uint)__bfloat16_as_ushort(__float2bfloat16_rn(b));
    return (hi << 16) | lo;
}

__global__ void prep_kernel(const float* __restrict__ w0, const float* __restrict__ w1,
                            const float* __restrict__ w2, const float* __restrict__ wih,
                            const float* __restrict__ whh)
{
    int i0 = blockIdx.x * blockDim.x + threadIdx.x;
    int stride = gridDim.x * blockDim.x;

    // w0 tiles: tile = mt*9+kt; element (r,c) at tile*384 + r*24 + c (c<16 valid)
    // K index 0 -> col0 (t_hi), 1..128 -> h, 129 -> col0 again (t_lo), else 0
    for (int idx = i0; idx < 144 * 384; idx += stride) {
        int tile = idx / 384, e = idx % 384, r = e / 24, c = e % 24;
        float v = 0.f;
        if (c < 16) {
            int mt = tile / 9, kt = tile % 9;
            int R = 16 * mt + r, K = 16 * kt + c;
            if (K < 129)       v = w0[R * 129 + K];
            else if (K == 129) v = w0[R * 129];
        }
        g_w0t[idx] = __bfloat16_as_ushort(__float2bfloat16_rn(v));
    }
    // w2 tiles: tile = mt*16+kt
    for (int idx = i0; idx < 128 * 384; idx += stride) {
        int tile = idx / 384, e = idx % 384, r = e / 24, c = e % 24;
        float v = 0.f;
        if (c < 16) {
            int mt = tile >> 4, kt = tile & 15;
            int R = 16 * mt + r, K = 16 * kt + c;
            v = w2[R * 256 + K];
        }
        g_w2t[idx] = __bfloat16_as_ushort(__float2bfloat16_rn(v));
    }
    // w1 fragments: idx = t*64 + kt*4 + i
    for (int idx = i0; idx < 512 * 64; idx += stride) {
        int t = idx >> 6, rem = idx & 63, kt = rem >> 2, i = rem & 3;
        int wid = t >> 5, lane = t & 31, g = lane >> 2, tig = lane & 3;
        int R = 16 * wid + g + ((i & 1) ? 8 : 0);
        int K = 16 * kt + 2 * tig + ((i & 2) ? 8 : 0);
        ((uint*)g_w1f)[idx] = pk_bf2(w1[R * 256 + K], w1[R * 256 + K + 1]);
    }
    // GRU fp32 packs
    for (int idx = i0; idx < 9 * 384; idx += stride) {
        int k4 = idx / 384, j = idx % 384, k = 4 * k4;
        float4 v;
        v.x = (k + 0 < 33) ? wih[j * 33 + k + 0] : 0.f;
        v.y = (k + 1 < 33) ? wih[j * 33 + k + 1] : 0.f;
        v.z = (k + 2 < 33) ? wih[j * 33 + k + 2] : 0.f;
        v.w = (k + 3 < 33) ? wih[j * 33 + k + 3] : 0.f;
        g_wihq[idx] = v;
    }
    for (int idx = i0; idx < 32 * 384; idx += stride) {
        int k4 = idx / 384, j = idx % 384, k = 4 * k4;
        g_whhq[idx] = make_float4(whh[j * 128 + k], whh[j * 128 + k + 1],
                                  whh[j * 128 + k + 2], whh[j * 128 + k + 3]);
    }
}

// ---------------- helpers ----------------
__device__ __forceinline__ uint smem_u32(const void* p) {
    return (uint)__cvta_generic_to_shared(p);
}
__device__ __forceinline__ void ldsm4(uint& r0, uint& r1, uint& r2, uint& r3, uint addr) {
    asm volatile("ldmatrix.sync.aligned.m8n8.x4.shared.b16 {%0,%1,%2,%3}, [%4];"
                 : "=r"(r0), "=r"(r1), "=r"(r2), "=r"(r3) : "r"(addr));
}
__device__ __forceinline__ void mma16816(float* d,
                                         uint a0, uint a1, uint a2, uint a3,
                                         uint b0, uint b1) {
    asm volatile("mma.sync.aligned.m16n8k16.row.col.f32.bf16.bf16.f32 "
                 "{%0,%1,%2,%3}, {%4,%5,%6,%7}, {%8,%9}, {%0,%1,%2,%3};"
                 : "+f"(d[0]), "+f"(d[1]), "+f"(d[2]), "+f"(d[3])
                 : "r"(a0), "r"(a1), "r"(a2), "r"(a3), "r"(b0), "r"(b1));
}
__device__ __forceinline__ float tanh_fast(float x) {
    float y; asm("tanh.approx.f32 %0, %1;" : "=f"(y) : "f"(x)); return y;
}
__device__ __forceinline__ float softplus_fast(float x) {
    return fmaxf(x, 0.f) + __logf(1.f + __expf(-fabsf(x)));
}
__device__ __forceinline__ float sigmoid_fast(float x) { return 1.f / (1.f + __expf(-x)); }
__device__ __forceinline__ float sigmoidp(float x) { return 1.f / (1.f + expf(-x)); }
__device__ __forceinline__ unsigned short bf16u(float v) {
    return __bfloat16_as_ushort(__float2bfloat16_rn(v));
}
__device__ __forceinline__ float bf2f(unsigned short u) {
    return __uint_as_float(((uint)u) << 16);
}

// dynamic smem: phase 1 = whh fp32 (196608B); phase 2 = w0 tiles (110592B) + w2 tiles (98304B)
#define DYN_SMEM_BYTES 208896
#define W2_SMEM_OFF    110592

__global__ void __launch_bounds__(512, 1)
solve_kernel(const float* __restrict__ ts, const float* __restrict__ ys,
             const float* __restrict__ scale,
             const float* __restrict__ mlp_b0, const float* __restrict__ mlp_b1,
             const float* __restrict__ mlp_b2,
             const float* __restrict__ gru_b, const float* __restrict__ gru_bn,
             const float* __restrict__ htl_w, const float* __restrict__ htl_b,
             const float* __restrict__ htb_w, const float* __restrict__ htb_b,
             const float* __restrict__ lti_w, const float* __restrict__ lti_b,
             const float* __restrict__ lth_w, const float* __restrict__ lth_b,
             float* __restrict__ out)
{
    const int b   = blockIdx.x;
    const int tid = threadIdx.x;
    const int lane = tid & 31, wid = tid >> 5;
    const int g = lane >> 2, tig = lane & 3;

    extern __shared__ __align__(16) char s_dyn[];

    __shared__ __align__(16) float s_xg[36];
    __shared__ __align__(16) float s_hid[128];
    __shared__ float s_ih[384], s_hh[384];
    __shared__ __align__(16) float s_y[136];
    __shared__ float s_k[6][136];                        // k-stage history (row 5 = scratch)
    __shared__ __align__(4) unsigned short s_xb[144];    // bf16 [t_hi, h(128), t_lo, 0..]
    __shared__ __align__(4) unsigned short s_a0b[256];
    __shared__ __align__(4) unsigned short s_a1b[256];
    __shared__ float s_z0[64];
    __shared__ float s_beta;

    const int OFF_H = 64 * 64 * 5;
    const int OFF_Z = OFF_H + 64 * 64 * 128;

    // ---- phase 1: whh into smem ----
    float4* s_whh = (float4*)s_dyn;
    for (int i = tid; i < 32 * 384; i += 512) s_whh[i] = g_whhq[i];

    const float gb  = (tid < 384) ? gru_b[tid]  : 0.f;
    const float gbn = (tid < 128) ? gru_bn[tid] : 0.f;

    if (tid < 128) s_hid[tid] = 0.f;
    if (tid >= 33 && tid < 36) s_xg[tid] = 0.f;
    // zero-init k history (avoid NaN*0 from garbage smem)
    for (int i = tid; i < 6 * 136; i += 512) ((float*)s_k)[i] = 0.f;
    __syncthreads();

    // ---------------- GRU over reversed sequence ----------------
    for (int step = 0; step < 64; ++step) {
        int r = 63 - step;
        if (tid == 0) s_xg[0] = ts[b * 64 + r];
        if (tid >= 1 && tid < 33) s_xg[tid] = ys[(b * 64 + r) * 32 + (tid - 1)];
        __syncthreads();

        if (tid < 384) {
            const float4* xg4 = (const float4*)s_xg;
            const float4* h4  = (const float4*)s_hid;
            int row = tid;
            float a0 = gb, a1 = 0.f;
            #pragma unroll
            for (int k = 0; k < 9; ++k) {
                float4 w = g_wihq[k * 384 + row];
                float4 x = xg4[k];
                a0 = fmaf(w.x, x.x, fmaf(w.z, x.z, a0));
                a1 = fmaf(w.y, x.y, fmaf(w.w, x.w, a1));
            }
            float c0 = 0.f, c1 = 0.f;
            #pragma unroll 8
            for (int k = 0; k < 32; ++k) {
                float4 w = s_whh[k * 384 + row];
                float4 x = h4[k];
                c0 = fmaf(w.x, x.x, fmaf(w.z, x.z, c0));
                c1 = fmaf(w.y, x.y, fmaf(w.w, x.w, c1));
            }
            s_ih[row] = a0 + a1;
            s_hh[row] = c0 + c1;
        }
        __syncthreads();
        if (tid < 128) {
            float rr = sigmoidp(s_ih[tid] + s_hh[tid]);
            float zz = sigmoidp(s_ih[128 + tid] + s_hh[128 + tid]);
            float nn = tanhf(s_ih[256 + tid] + rr * (s_hh[256 + tid] + gbn));
            s_hid[tid] = nn + zz * (s_hid[tid] - nn);
        }
        __syncthreads();
    }

    // ---------------- head ----------------
    if (tid < 64) {
        float acc = htl_b[tid];
        #pragma unroll 8
        for (int k = 0; k < 128; ++k) acc = fmaf(htl_w[tid * 128 + k], s_hid[k], acc);
        s_z0[tid] = acc;
        out[OFF_Z + b * 64 + tid] = acc;
    }
    __syncthreads();
    if (tid < 128) {
        float acc = lth_b[tid];
        #pragma unroll 8
        for (int k = 0; k < 64; ++k) acc = fmaf(lth_w[tid * 64 + k], s_z0[k], acc);
        s_y[5 + tid] = acc;
    }
    if (tid == 0) {
        float lg[5], mx = -1e30f;
        #pragma unroll
        for (int m = 0; m < 5; ++m) {
            float acc = lti_b[m];
            for (int k = 0; k < 64; ++k) acc = fmaf(lti_w[m * 64 + k], s_z0[k], acc);
            lg[m] = acc; mx = fmaxf(mx, acc);
        }
        float sum = 0.f;
        #pragma unroll
        for (int m = 0; m < 5; ++m) { float t = expf(lg[m] - mx); s_y[m] = t; sum += t; }
        #pragma unroll
        for (int m = 0; m < 5; ++m) s_y[m] /= sum;
    }
    __syncthreads();   // done with s_whh; s_y ready

    // ---- phase 2: MLP weight tiles into smem ----
    {
        uint4* dst0 = (uint4*)s_dyn;
        const uint4* src0 = (const uint4*)g_w0t;
        for (int i = tid; i < 144 * 384 / 8; i += 512) dst0[i] = src0[i];
        uint4* dst2 = (uint4*)(s_dyn + W2_SMEM_OFF);
        const uint4* src2 = (const uint4*)g_w2t;
        for (int i = tid; i < 128 * 384 / 8; i += 512) dst2[i] = src2[i];
    }

    // w1 fragments into registers
    uint4 w1f[16];
    #pragma unroll
    for (int j = 0; j < 16; ++j) w1f[j] = g_w1f[tid * 16 + j];

    // per-thread constants
    const int rowg = 16 * wid + g;
    const float b0lo = mlp_b0[rowg], b0hi = mlp_b0[rowg + 8];
    const float b1lo = mlp_b1[rowg], b1hi = mlp_b1[rowg + 8];
    float b2lo = 0.f, b2hi = 0.f;
    if (wid < 8) { b2lo = mlp_b2[rowg]; b2hi = mlp_b2[rowg + 8]; }
    const float scl = scale[0];

    float hw0 = 0.f, hw1 = 0.f, hw2 = 0.f, hw3 = 0.f, htbb = 0.f;
    if (wid == 15) {
        hw0 = htb_w[lane]; hw1 = htb_w[lane + 32];
        hw2 = htb_w[lane + 64]; hw3 = htb_w[lane + 96];
        htbb = htb_b[0];
    }

    const uint laneoff = (uint)((lane & 15) * 48 + (lane >> 4) * 16);
    const uint w0base = smem_u32(s_dyn) + (uint)(wid * 9 * 768) + laneoff;
    const uint w2base = smem_u32(s_dyn) + W2_SMEM_OFF + (uint)(wid * 16 * 768) + laneoff;

    // init s_xb from initial state; t=0; y-base registers
    if (tid < 128) s_xb[1 + tid] = bf16u(s_y[5 + tid]);
    if (tid == 256) { s_xb[0] = 0; s_xb[129] = 0; }
    if (tid >= 130 && tid < 144) s_xb[tid] = 0;
    float ya = 0.f, yb = 0.f;
    if (wid < 8 && tig == 0) { ya = s_y[5 + rowg]; yb = s_y[13 + rowg]; }
    // SEIAR base + stage state in warp 15 lane 0 registers
    float yS0 = 0, yS1 = 0, yS2 = 0, yS3 = 0, yS4 = 0;   // y-base
    float tS0 = 0, tS1 = 0, tS2 = 0, tS3 = 0, tS4 = 0;   // stage state
    if (wid == 15 && lane == 0) {
        yS0 = s_y[0]; yS1 = s_y[1]; yS2 = s_y[2]; yS3 = s_y[3]; yS4 = s_y[4];
        tS0 = yS0; tS1 = yS1; tS2 = yS2; tS3 = yS3; tS4 = yS4;
    }
    __syncthreads();

    // ---------------- tsit5: 6 stages, 3 barriers each ----------------
    auto tsit5 = [&](float tt, float h, float t_after) {
        #pragma unroll 1
        for (int s = 0; s < 6; ++s) {
            // --- phase A: layer 0 (+ beta on warp 15); 2 acc sets ---
            {
                const uint* x32 = (const uint*)s_xb;
                float d[4] = {}, f[4] = {};
                #pragma unroll
                for (int kt = 0; kt < 9; ++kt) {
                    uint a0, a1, a2, a3;
                    ldsm4(a0, a1, a2, a3, w0base + (uint)(kt * 768));
                    uint p0 = 0, p1 = 0;
                    if (lane < 4) { p0 = x32[8 * kt + lane]; p1 = x32[8 * kt + 4 + lane]; }
                    if (kt & 1) mma16816(f, a0, a1, a2, a3, p0, p1);
                    else        mma16816(d, a0, a1, a2, a3, p0, p1);
                }
                if (wid == 15) {
                    float p = fmaf(hw0, bf2f(s_xb[1 + lane]),
                              fmaf(hw1, bf2f(s_xb[33 + lane]),
                              fmaf(hw2, bf2f(s_xb[65 + lane]),
                                   hw3 * bf2f(s_xb[97 + lane]))));
                    #pragma unroll
                    for (int o = 16; o > 0; o >>= 1) p += __shfl_xor_sync(0xffffffffu, p, o);
                    if (lane == 0) s_beta = sigmoid_fast(0.01f * (p + htbb));
                }
                if (tig == 0) {
                    s_a0b[rowg]     = bf16u(softplus_fast(d[0] + f[0] + b0lo));
                    s_a0b[rowg + 8] = bf16u(softplus_fast(d[2] + f[2] + b0hi));
                }
            }
            __syncthreads();

            // --- phase B: layer 1 (A fragments in registers); 4 acc sets (chain 4) ---
            {
                const uint* y32 = (const uint*)s_a0b;
                float ac[4][4] = {};
                #pragma unroll
                for (int kt = 0; kt < 16; ++kt) {
                    uint p0 = 0, p1 = 0;
                    if (lane < 4) { p0 = y32[8 * kt + lane]; p1 = y32[8 * kt + 4 + lane]; }
                    mma16816(ac[kt & 3], w1f[kt].x, w1f[kt].y, w1f[kt].z, w1f[kt].w, p0, p1);
                }
                if (tig == 0) {
                    float d0 = (ac[0][0] + ac[1][0]) + (ac[2][0] + ac[3][0]);
                    float d2 = (ac[0][2] + ac[1][2]) + (ac[2][2] + ac[3][2]);
                    s_a1b[rowg]     = bf16u(softplus_fast(d0 + b1lo));
                    s_a1b[rowg + 8] = bf16u(softplus_fast(d2 + b1hi));
                }
            }
            __syncthreads();

            // --- phase C: layer 2 (full-K, warps 0-7, 2 acc sets) fused with RK combine;
            //     k-history prefetched at phase start (zero-padded coeff table) ---
            if (wid < 8) {
                // prefetch k history (LDS hidden under the MMA loop)
                float khA[5], khB[5];
                #pragma unroll
                for (int j = 0; j < 5; ++j) {
                    khA[j] = s_k[j][5 + rowg];
                    khB[j] = s_k[j][13 + rowg];
                }
                const uint* y32 = (const uint*)s_a1b;
                float d[4] = {}, f[4] = {};
                #pragma unroll
                for (int kt = 0; kt < 16; ++kt) {
                    uint a0, a1, a2, a3;
                    ldsm4(a0, a1, a2, a3, w2base + (uint)(kt * 768));
                    uint p0 = 0, p1 = 0;
                    if (lane < 4) { p0 = y32[8 * kt + lane]; p1 = y32[8 * kt + 4 + lane]; }
                    if (kt & 1) mma16816(f, a0, a1, a2, a3, p0, p1);
                    else        mma16816(d, a0, a1, a2, a3, p0, p1);
                }
                if (tig == 0) {
                    float kA = scl * (0.1f * tanh_fast(1e-4f * (d[0] + f[0] + b2lo)));
                    float kB = scl * (0.1f * tanh_fast(1e-4f * (d[2] + f[2] + b2hi)));
                    float cd = c_DIAG[s];
                    float sA = cd * kA, sB = cd * kB;
                    #pragma unroll
                    for (int j = 0; j < 5; ++j) {
                        float c = c_OFF[s][j];
                        sA += c * khA[j];
                        sB += c * khB[j];
                    }
                    s_k[s][5 + rowg] = kA;    // s==5 writes scratch row, never read
                    s_k[s][13 + rowg] = kB;
                    float vA = ya + h * sA, vB = yb + h * sB;
                    s_xb[1 + rowg] = bf16u(vA);
                    s_xb[9 + rowg] = bf16u(vB);
                    if (s == 5) { ya = vA; yb = vB; s_y[5 + rowg] = vA; s_y[13 + rowg] = vB; }
                }
            } else if (wid == 15 && lane == 0) {
                // SEIAR: all 5 components serially in one lane
                float kh[5][5];
                #pragma unroll
                for (int j = 0; j < 5; ++j)
                    #pragma unroll
                    for (int i = 0; i < 5; ++i) kh[j][i] = s_k[j][i];
                float S = tS0, E = tS1, I = tS2, A_ = tS3;
                float LL = 0.5f * I + A_;
                float bSL = s_beta * S * LL;
                float k0v = -bSL;
                float k1v = bSL - 0.526f * E;
                float k2v = fmaf((float)(0.667 * 0.526), E, -(0.244f * I));
                float k3v = fmaf((float)((1.0 - 0.667) * 0.526), E, -(0.244f * A_));
                float k4v = fmaf((float)(0.98 * 0.244), I, 0.244f * A_);
                float cd = c_DIAG[s];
                float s0 = cd * k0v, s1 = cd * k1v, s2 = cd * k2v;
                float s3 = cd * k3v, s4 = cd * k4v;
                #pragma unroll
                for (int j = 0; j < 5; ++j) {
                    float c = c_OFF[s][j];
                    s0 += c * kh[j][0]; s1 += c * kh[j][1]; s2 += c * kh[j][2];
                    s3 += c * kh[j][3]; s4 += c * kh[j][4];
                }
                s_k[s][0] = k0v; s_k[s][1] = k1v; s_k[s][2] = k2v;
                s_k[s][3] = k3v; s_k[s][4] = k4v;
                tS0 = yS0 + h * s0; tS1 = yS1 + h * s1; tS2 = yS2 + h * s2;
                tS3 = yS3 + h * s3; tS4 = yS4 + h * s4;
                if (s == 5) {
                    yS0 = tS0; yS1 = tS1; yS2 = tS2; yS3 = tS3; yS4 = tS4;
                    s_y[0] = tS0; s_y[1] = tS1; s_y[2] = tS2; s_y[3] = tS3; s_y[4] = tS4;
                }
                // t-slot for next vf eval
                float tn = (s < 5) ? tt + c_CC[s] * h : t_after;
                unsigned short u = bf16u(tn);
                s_xb[0] = u;
                s_xb[129] = bf16u(tn - bf2f(u));
            }
            __syncthreads();
        }
    };

    float t0v = 0.f;
    for (int st = 0; st < 64; ++st) {
        float tn = ts[b * 64 + st];
        float dt = (tn - t0v) * 0.5f;    // K_SUB = 2
        tsit5(t0v,      dt, t0v + dt);
        tsit5(t0v + dt, dt, tn);
        t0v = tn;
        if (tid < 5)   out[(b * 64 + st) * 5 + tid] = s_y[tid];
        if (tid < 128) out[OFF_H + (b * 64 + st) * 128 + tid] = s_y[5 + tid];
    }
}

extern "C" void kernel_launch(void* const* d_in, const int* in_sizes, int n_in,
                              void* d_out, int out_size) {
    const float* ts      = (const float*)d_in[0];
    const float* ys      = (const float*)d_in[1];
    const float* scale   = (const float*)d_in[2];
    const float* mlp_w0  = (const float*)d_in[3];
    const float* mlp_b0  = (const float*)d_in[4];
    const float* mlp_w1  = (const float*)d_in[5];
    const float* mlp_b1  = (const float*)d_in[6];
    const float* mlp_w2  = (const float*)d_in[7];
    const float* mlp_b2  = (const float*)d_in[8];
    const float* gru_wih = (const float*)d_in[9];
    const float* gru_whh = (const float*)d_in[10];
    const float* gru_b   = (const float*)d_in[11];
    const float* gru_bn  = (const float*)d_in[12];
    const float* htl_w   = (const float*)d_in[13];
    const float* htl_b   = (const float*)d_in[14];
    const float* htb_w   = (const float*)d_in[15];
    const float* htb_b   = (const float*)d_in[16];
    const float* lti_w   = (const float*)d_in[17];
    const float* lti_b   = (const float*)d_in[18];
    const float* lth_w   = (const float*)d_in[19];
    const float* lth_b   = (const float*)d_in[20];

    static int attr_set = 0;
    if (!attr_set) {
        cudaFuncSetAttribute(solve_kernel,
                             cudaFuncAttributeMaxDynamicSharedMemorySize,
                             DYN_SMEM_BYTES);
        attr_set = 1;
    }

    prep_kernel<<<96, 256>>>(mlp_w0, mlp_w1, mlp_w2, gru_wih, gru_whh);
    solve_kernel<<<64, 512, DYN_SMEM_BYTES>>>(ts, ys, scale, mlp_b0, mlp_b1, mlp_b2,
                              gru_b, gru_bn, htl_w, htl_b, htb_w, htb_b,
                              lti_w, lti_b, lth_w, lth_b, (float*)d_out);
}

// round 13
// speedup vs baseline: 1.3218x; 1.0253x over previous
#include <cuda_runtime.h>
#include <cuda_bf16.h>

// Dims: B=64, T=64, D=32, H=128, W=256, L=64, K_SUB=2
typedef unsigned uint;

// ---------------- device scratch ----------------
__device__ float4 g_wihq[ 9 * 384];            // GRU input weights fp32 packed
__device__ float4 g_whhq[32 * 384];            // GRU hidden weights fp32 packed
// MLP weight tiles for ldmatrix: 16x16 bf16 tiles, row stride 48B (24 ushorts, 16 used)
__device__ unsigned short g_w0t[144 * 384];    // (256,144): 16 m-tiles x 9 k-tiles
__device__ unsigned short g_w2t[128 * 384];    // (128,256): 8 m-tiles x 16 k-tiles
// w1 A-fragments, per-thread: 16 k-tiles x 4 regs
__device__ uint4 g_w1f[512 * 16];

// RK coefficient tables (row s: coeffs for k0..k5; stage s uses k0..ks)
__constant__ float c_AT[6][6] = {
    {0.161f, 0, 0, 0, 0, 0},
    {(float)-0.008480655492356989, (float)0.335480655492357, 0, 0, 0, 0},
    {(float)2.8971530571054935, (float)-6.359448489975075, (float)4.3622954328695815, 0, 0, 0},
    {(float)5.325864828439257, (float)-11.748883564062828, (float)7.4955393428898365,
     (float)-0.09249506636175525, 0, 0},
    {(float)5.86145544294642, (float)-12.92096931784711, (float)8.159367898576159,
     (float)-0.071584973281401, (float)-0.028269050394068383, 0},
    {(float)0.09646076681806523, 0.01f, (float)0.4798896504144996,
     (float)1.379008574103742, (float)-3.290069515436081, (float)2.324710524099774}};
__constant__ float c_CC[5] = {0.161f, 0.327f, 0.9f, (float)0.9800255409045097, 1.0f};

__device__ __forceinline__ uint pk_bf2(float a, float b) {
    uint lo = (uint)__bfloat16_as_ushort(__float2bfloat16_rn(a));
    uint hi = (uint)__bfloat16_as_ushort(__float2bfloat16_rn(b));
    return (hi << 16) | lo;
}

__global__ void prep_kernel(const float* __restrict__ w0, const float* __restrict__ w1,
                            const float* __restrict__ w2, const float* __restrict__ wih,
                            const float* __restrict__ whh)
{
    int i0 = blockIdx.x * blockDim.x + threadIdx.x;
    int stride = gridDim.x * blockDim.x;

    // w0 tiles: tile = mt*9+kt; element (r,c) at tile*384 + r*24 + c (c<16 valid)
    // K index 0 -> col0 (t_hi), 1..128 -> h, 129 -> col0 again (t_lo), else 0
    for (int idx = i0; idx < 144 * 384; idx += stride) {
        int tile = idx / 384, e = idx % 384, r = e / 24, c = e % 24;
        float v = 0.f;
        if (c < 16) {
            int mt = tile / 9, kt = tile % 9;
            int R = 16 * mt + r, K = 16 * kt + c;
            if (K < 129)       v = w0[R * 129 + K];
            else if (K == 129) v = w0[R * 129];
        }
        g_w0t[idx] = __bfloat16_as_ushort(__float2bfloat16_rn(v));
    }
    // w2 tiles: tile = mt*16+kt
    for (int idx = i0; idx < 128 * 384; idx += stride) {
        int tile = idx / 384, e = idx % 384, r = e / 24, c = e % 24;
        float v = 0.f;
        if (c < 16) {
            int mt = tile >> 4, kt = tile & 15;
            int R = 16 * mt + r, K = 16 * kt + c;
            v = w2[R * 256 + K];
        }
        g_w2t[idx] = __bfloat16_as_ushort(__float2bfloat16_rn(v));
    }
    // w1 fragments: idx = t*64 + kt*4 + i
    for (int idx = i0; idx < 512 * 64; idx += stride) {
        int t = idx >> 6, rem = idx & 63, kt = rem >> 2, i = rem & 3;
        int wid = t >> 5, lane = t & 31, g = lane >> 2, tig = lane & 3;
        int R = 16 * wid + g + ((i & 1) ? 8 : 0);
        int K = 16 * kt + 2 * tig + ((i & 2) ? 8 : 0);
        ((uint*)g_w1f)[idx] = pk_bf2(w1[R * 256 + K], w1[R * 256 + K + 1]);
    }
    // GRU fp32 packs
    for (int idx = i0; idx < 9 * 384; idx += stride) {
        int k4 = idx / 384, j = idx % 384, k = 4 * k4;
        float4 v;
        v.x = (k + 0 < 33) ? wih[j * 33 + k + 0] : 0.f;
        v.y = (k + 1 < 33) ? wih[j * 33 + k + 1] : 0.f;
        v.z = (k + 2 < 33) ? wih[j * 33 + k + 2] : 0.f;
        v.w = (k + 3 < 33) ? wih[j * 33 + k + 3] : 0.f;
        g_wihq[idx] = v;
    }
    for (int idx = i0; idx < 32 * 384; idx += stride) {
        int k4 = idx / 384, j = idx % 384, k = 4 * k4;
        g_whhq[idx] = make_float4(whh[j * 128 + k], whh[j * 128 + k + 1],
                                  whh[j * 128 + k + 2], whh[j * 128 + k + 3]);
    }
}

// ---------------- helpers ----------------
__device__ __forceinline__ uint smem_u32(const void* p) {
    return (uint)__cvta_generic_to_shared(p);
}
__device__ __forceinline__ void ldsm4(uint& r0, uint& r1, uint& r2, uint& r3, uint addr) {
    asm volatile("ldmatrix.sync.aligned.m8n8.x4.shared.b16 {%0,%1,%2,%3}, [%4];"
                 : "=r"(r0), "=r"(r1), "=r"(r2), "=r"(r3) : "r"(addr));
}
__device__ __forceinline__ void mma16816(float* d,
                                         uint a0, uint a1, uint a2, uint a3,
                                         uint b0, uint b1) {
    asm volatile("mma.sync.aligned.m16n8k16.row.col.f32.bf16.bf16.f32 "
                 "{%0,%1,%2,%3}, {%4,%5,%6,%7}, {%8,%9}, {%0,%1,%2,%3};"
                 : "+f"(d[0]), "+f"(d[1]), "+f"(d[2]), "+f"(d[3])
                 : "r"(a0), "r"(a1), "r"(a2), "r"(a3), "r"(b0), "r"(b1));
}
__device__ __forceinline__ float tanh_fast(float x) {
    float y; asm("tanh.approx.f32 %0, %1;" : "=f"(y) : "f"(x)); return y;
}
__device__ __forceinline__ float softplus_fast(float x) {
    return fmaxf(x, 0.f) + __logf(1.f + __expf(-fabsf(x)));
}
__device__ __forceinline__ float sigmoid_fast(float x) { return 1.f / (1.f + __expf(-x)); }
__device__ __forceinline__ float sigmoidp(float x) { return 1.f / (1.f + expf(-x)); }
__device__ __forceinline__ unsigned short bf16u(float v) {
    return __bfloat16_as_ushort(__float2bfloat16_rn(v));
}
__device__ __forceinline__ float bf2f(unsigned short u) {
    return __uint_as_float(((uint)u) << 16);
}

// dynamic smem: phase 1 = whh fp32 (196608B); phase 2 = w0 tiles (110592B) + w2 tiles (98304B)
#define DYN_SMEM_BYTES 208896
#define W2_SMEM_OFF    110592

__global__ void __launch_bounds__(512, 1)
solve_kernel(const float* __restrict__ ts, const float* __restrict__ ys,
             const float* __restrict__ scale,
             const float* __restrict__ mlp_b0, const float* __restrict__ mlp_b1,
             const float* __restrict__ mlp_b2,
             const float* __restrict__ gru_b, const float* __restrict__ gru_bn,
             const float* __restrict__ htl_w, const float* __restrict__ htl_b,
             const float* __restrict__ htb_w, const float* __restrict__ htb_b,
             const float* __restrict__ lti_w, const float* __restrict__ lti_b,
             const float* __restrict__ lth_w, const float* __restrict__ lth_b,
             float* __restrict__ out)
{
    const int b   = blockIdx.x;
    const int tid = threadIdx.x;
    const int lane = tid & 31, wid = tid >> 5;
    const int g = lane >> 2, tig = lane & 3;

    extern __shared__ __align__(16) char s_dyn[];

    __shared__ __align__(16) float s_xg[36];
    __shared__ __align__(16) float s_hid[128];
    __shared__ float s_ih[384], s_hh[384];
    __shared__ __align__(16) float s_y[136];
    __shared__ float s_k[5][136];                        // k-stage history
    __shared__ __align__(4) unsigned short s_xb[144];    // bf16 [t_hi, h(128), t_lo, 0..]
    __shared__ __align__(4) unsigned short s_a0b[256];
    __shared__ __align__(4) unsigned short s_a1b[256];
    __shared__ float s_z0[64];
    __shared__ float s_beta;

    const int OFF_H = 64 * 64 * 5;
    const int OFF_Z = OFF_H + 64 * 64 * 128;

    // ---- phase 1: whh into smem ----
    float4* s_whh = (float4*)s_dyn;
    for (int i = tid; i < 32 * 384; i += 512) s_whh[i] = g_whhq[i];

    const float gb  = (tid < 384) ? gru_b[tid]  : 0.f;
    const float gbn = (tid < 128) ? gru_bn[tid] : 0.f;

    if (tid < 128) s_hid[tid] = 0.f;
    if (tid >= 33 && tid < 36) s_xg[tid] = 0.f;
    __syncthreads();

    // ---------------- GRU over reversed sequence ----------------
    for (int step = 0; step < 64; ++step) {
        int r = 63 - step;
        if (tid == 0) s_xg[0] = ts[b * 64 + r];
        if (tid >= 1 && tid < 33) s_xg[tid] = ys[(b * 64 + r) * 32 + (tid - 1)];
        __syncthreads();

        if (tid < 384) {
            const float4* xg4 = (const float4*)s_xg;
            const float4* h4  = (const float4*)s_hid;
            int row = tid;
            float a0 = gb, a1 = 0.f;
            #pragma unroll
            for (int k = 0; k < 9; ++k) {
                float4 w = g_wihq[k * 384 + row];
                float4 x = xg4[k];
                a0 = fmaf(w.x, x.x, fmaf(w.z, x.z, a0));
                a1 = fmaf(w.y, x.y, fmaf(w.w, x.w, a1));
            }
            float c0 = 0.f, c1 = 0.f;
            #pragma unroll 8
            for (int k = 0; k < 32; ++k) {
                float4 w = s_whh[k * 384 + row];
                float4 x = h4[k];
                c0 = fmaf(w.x, x.x, fmaf(w.z, x.z, c0));
                c1 = fmaf(w.y, x.y, fmaf(w.w, x.w, c1));
            }
            s_ih[row] = a0 + a1;
            s_hh[row] = c0 + c1;
        }
        __syncthreads();
        if (tid < 128) {
            float rr = sigmoidp(s_ih[tid] + s_hh[tid]);
            float zz = sigmoidp(s_ih[128 + tid] + s_hh[128 + tid]);
            float nn = tanhf(s_ih[256 + tid] + rr * (s_hh[256 + tid] + gbn));
            s_hid[tid] = nn + zz * (s_hid[tid] - nn);
        }
        __syncthreads();
    }

    // ---------------- head ----------------
    if (tid < 64) {
        float acc = htl_b[tid];
        #pragma unroll 8
        for (int k = 0; k < 128; ++k) acc = fmaf(htl_w[tid * 128 + k], s_hid[k], acc);
        s_z0[tid] = acc;
        out[OFF_Z + b * 64 + tid] = acc;
    }
    __syncthreads();
    if (tid < 128) {
        float acc = lth_b[tid];
        #pragma unroll 8
        for (int k = 0; k < 64; ++k) acc = fmaf(lth_w[tid * 64 + k], s_z0[k], acc);
        s_y[5 + tid] = acc;
    }
    if (tid == 0) {
        float lg[5], mx = -1e30f;
        #pragma unroll
        for (int m = 0; m < 5; ++m) {
            float acc = lti_b[m];
            for (int k = 0; k < 64; ++k) acc = fmaf(lti_w[m * 64 + k], s_z0[k], acc);
            lg[m] = acc; mx = fmaxf(mx, acc);
        }
        float sum = 0.f;
        #pragma unroll
        for (int m = 0; m < 5; ++m) { float t = expf(lg[m] - mx); s_y[m] = t; sum += t; }
        #pragma unroll
        for (int m = 0; m < 5; ++m) s_y[m] /= sum;
    }
    __syncthreads();   // done with s_whh; s_y ready

    // ---- phase 2: MLP weight tiles into smem ----
    {
        uint4* dst0 = (uint4*)s_dyn;
        const uint4* src0 = (const uint4*)g_w0t;
        for (int i = tid; i < 144 * 384 / 8; i += 512) dst0[i] = src0[i];
        uint4* dst2 = (uint4*)(s_dyn + W2_SMEM_OFF);
        const uint4* src2 = (const uint4*)g_w2t;
        for (int i = tid; i < 128 * 384 / 8; i += 512) dst2[i] = src2[i];
    }

    // w1 fragments into registers
    uint4 w1f[16];
    #pragma unroll
    for (int j = 0; j < 16; ++j) w1f[j] = g_w1f[tid * 16 + j];

    // per-thread constants
    const int rowg = 16 * wid + g;
    const float b0lo = mlp_b0[rowg], b0hi = mlp_b0[rowg + 8];
    const float b1lo = mlp_b1[rowg], b1hi = mlp_b1[rowg + 8];
    float b2lo = 0.f, b2hi = 0.f;
    if (wid < 8) { b2lo = mlp_b2[rowg]; b2hi = mlp_b2[rowg + 8]; }
    const float scl = scale[0];

    float hw0 = 0.f, hw1 = 0.f, hw2 = 0.f, hw3 = 0.f, htbb = 0.f;
    if (wid == 15) {
        hw0 = htb_w[lane]; hw1 = htb_w[lane + 32];
        hw2 = htb_w[lane + 64]; hw3 = htb_w[lane + 96];
        htbb = htb_b[0];
    }

    const uint laneoff = (uint)((lane & 15) * 48 + (lane >> 4) * 16);
    const uint w0base = smem_u32(s_dyn) + (uint)(wid * 9 * 768) + laneoff;
    const uint w2base = smem_u32(s_dyn) + W2_SMEM_OFF + (uint)(wid * 16 * 768) + laneoff;

    // init s_xb from initial state; t=0; y-base registers
    if (tid < 128) s_xb[1 + tid] = bf16u(s_y[5 + tid]);
    if (tid == 256) { s_xb[0] = 0; s_xb[129] = 0; }
    if (tid >= 130 && tid < 144) s_xb[tid] = 0;
    float ya = 0.f, yb = 0.f;
    if (wid < 8 && tig == 0) { ya = s_y[5 + rowg]; yb = s_y[13 + rowg]; }
    // SEIAR base + stage state in warp 15 lane 0 registers
    float yS0 = 0, yS1 = 0, yS2 = 0, yS3 = 0, yS4 = 0;   // y-base
    float tS0 = 0, tS1 = 0, tS2 = 0, tS3 = 0, tS4 = 0;   // stage state
    if (wid == 15 && lane == 0) {
        yS0 = s_y[0]; yS1 = s_y[1]; yS2 = s_y[2]; yS3 = s_y[3]; yS4 = s_y[4];
        tS0 = yS0; tS1 = yS1; tS2 = yS2; tS3 = yS3; tS4 = yS4;
    }
    __syncthreads();

    // ---------------- tsit5: 6 stages, 3 barriers each ----------------
    auto tsit5 = [&](float tt, float h, float t_after) {
        #pragma unroll 1
        for (int s = 0; s < 6; ++s) {
            // --- phase A: layer 0 (+ beta on warp 15); 2 acc sets ---
            {
                const uint* x32 = (const uint*)s_xb;
                float d[4] = {}, f[4] = {};
                #pragma unroll
                for (int kt = 0; kt < 9; ++kt) {
                    uint a0, a1, a2, a3;
                    ldsm4(a0, a1, a2, a3, w0base + (uint)(kt * 768));
                    uint p0 = 0, p1 = 0;
                    if (lane < 4) { p0 = x32[8 * kt + lane]; p1 = x32[8 * kt + 4 + lane]; }
                    if (kt & 1) mma16816(f, a0, a1, a2, a3, p0, p1);
                    else        mma16816(d, a0, a1, a2, a3, p0, p1);
                }
                if (wid == 15) {
                    float p = fmaf(hw0, bf2f(s_xb[1 + lane]),
                              fmaf(hw1, bf2f(s_xb[33 + lane]),
                              fmaf(hw2, bf2f(s_xb[65 + lane]),
                                   hw3 * bf2f(s_xb[97 + lane]))));
                    #pragma unroll
                    for (int o = 16; o > 0; o >>= 1) p += __shfl_xor_sync(0xffffffffu, p, o);
                    if (lane == 0) s_beta = sigmoid_fast(0.01f * (p + htbb));
                }
                if (tig == 0) {
                    s_a0b[rowg]     = bf16u(softplus_fast(d[0] + f[0] + b0lo));
                    s_a0b[rowg + 8] = bf16u(softplus_fast(d[2] + f[2] + b0hi));
                }
            }
            __syncthreads();

            // --- phase B: layer 1 (A fragments in registers); 4 acc sets (chain 4) ---
            {
                const uint* y32 = (const uint*)s_a0b;
                float ac[4][4] = {};
                #pragma unroll
                for (int kt = 0; kt < 16; ++kt) {
                    uint p0 = 0, p1 = 0;
                    if (lane < 4) { p0 = y32[8 * kt + lane]; p1 = y32[8 * kt + 4 + lane]; }
                    mma16816(ac[kt & 3], w1f[kt].x, w1f[kt].y, w1f[kt].z, w1f[kt].w, p0, p1);
                }
                if (tig == 0) {
                    float d0 = (ac[0][0] + ac[1][0]) + (ac[2][0] + ac[3][0]);
                    float d2 = (ac[0][2] + ac[1][2]) + (ac[2][2] + ac[3][2]);
                    s_a1b[rowg]     = bf16u(softplus_fast(d0 + b1lo));
                    s_a1b[rowg + 8] = bf16u(softplus_fast(d2 + b1hi));
                }
            }
            __syncthreads();

            // --- phase C: layer 2 (full-K, warps 0-7, 2 acc sets) fused with RK combine ---
            if (wid < 8) {
                const uint* y32 = (const uint*)s_a1b;
                float d[4] = {}, f[4] = {};
                #pragma unroll
                for (int kt = 0; kt < 16; ++kt) {
                    uint a0, a1, a2, a3;
                    ldsm4(a0, a1, a2, a3, w2base + (uint)(kt * 768));
                    uint p0 = 0, p1 = 0;
                    if (lane < 4) { p0 = y32[8 * kt + lane]; p1 = y32[8 * kt + 4 + lane]; }
                    if (kt & 1) mma16816(f, a0, a1, a2, a3, p0, p1);
                    else        mma16816(d, a0, a1, a2, a3, p0, p1);
                }
                if (tig == 0) {
                    float kA = scl * (0.1f * tanh_fast(1e-4f * (d[0] + f[0] + b2lo)));
                    float kB = scl * (0.1f * tanh_fast(1e-4f * (d[2] + f[2] + b2hi)));
                    float sA = c_AT[s][s] * kA, sB = c_AT[s][s] * kB;
                    #pragma unroll 1
                    for (int j = 0; j < s; ++j) {
                        sA += c_AT[s][j] * s_k[j][5 + rowg];
                        sB += c_AT[s][j] * s_k[j][13 + rowg];
                    }
                    if (s < 5) { s_k[s][5 + rowg] = kA; s_k[s][13 + rowg] = kB; }
                    float vA = ya + h * sA, vB = yb + h * sB;
                    s_xb[1 + rowg] = bf16u(vA);
                    s_xb[9 + rowg] = bf16u(vB);
                    if (s == 5) { ya = vA; yb = vB; s_y[5 + rowg] = vA; s_y[13 + rowg] = vB; }
                }
            } else if (wid == 15 && lane == 0) {
                // SEIAR: all 5 components serially in one lane (no warp coupling)
                float S = tS0, E = tS1, I = tS2, A_ = tS3;
                float LL = 0.5f * I + A_;
                float bSL = s_beta * S * LL;
                float k0v = -bSL;
                float k1v = bSL - 0.526f * E;
                float k2v = fmaf((float)(0.667 * 0.526), E, -(0.244f * I));
                float k3v = fmaf((float)((1.0 - 0.667) * 0.526), E, -(0.244f * A_));
                float k4v = fmaf((float)(0.98 * 0.244), I, 0.244f * A_);
                float s0 = c_AT[s][s] * k0v, s1 = c_AT[s][s] * k1v, s2 = c_AT[s][s] * k2v;
                float s3 = c_AT[s][s] * k3v, s4 = c_AT[s][s] * k4v;
                #pragma unroll 1
                for (int j = 0; j < s; ++j) {
                    float c = c_AT[s][j];
                    s0 += c * s_k[j][0]; s1 += c * s_k[j][1]; s2 += c * s_k[j][2];
                    s3 += c * s_k[j][3]; s4 += c * s_k[j][4];
                }
                if (s < 5) {
                    s_k[s][0] = k0v; s_k[s][1] = k1v; s_k[s][2] = k2v;
                    s_k[s][3] = k3v; s_k[s][4] = k4v;
                }
                tS0 = yS0 + h * s0; tS1 = yS1 + h * s1; tS2 = yS2 + h * s2;
                tS3 = yS3 + h * s3; tS4 = yS4 + h * s4;
                if (s == 5) {
                    yS0 = tS0; yS1 = tS1; yS2 = tS2; yS3 = tS3; yS4 = tS4;
                    s_y[0] = tS0; s_y[1] = tS1; s_y[2] = tS2; s_y[3] = tS3; s_y[4] = tS4;
                }
                // t-slot for next vf eval
                float tn = (s < 5) ? tt + c_CC[s] * h : t_after;
                unsigned short u = bf16u(tn);
                s_xb[0] = u;
                s_xb[129] = bf16u(tn - bf2f(u));
            }
            __syncthreads();
        }
    };

    float t0v = 0.f;
    for (int st = 0; st < 64; ++st) {
        float tn = ts[b * 64 + st];
        float dt = (tn - t0v) * 0.5f;    // K_SUB = 2
        tsit5(t0v,      dt, t0v + dt);
        tsit5(t0v + dt, dt, tn);
        t0v = tn;
        if (tid < 5)   out[(b * 64 + st) * 5 + tid] = s_y[tid];
        if (tid < 128) out[OFF_H + (b * 64 + st) * 128 + tid] = s_y[5 + tid];
    }
}

extern "C" void kernel_launch(void* const* d_in, const int* in_sizes, int n_in,
                              void* d_out, int out_size) {
    const float* ts      = (const float*)d_in[0];
    const float* ys      = (const float*)d_in[1];
    const float* scale   = (const float*)d_in[2];
    const float* mlp_w0  = (const float*)d_in[3];
    const float* mlp_b0  = (const float*)d_in[4];
    const float* mlp_w1  = (const float*)d_in[5];
    const float* mlp_b1  = (const float*)d_in[6];
    const float* mlp_w2  = (const float*)d_in[7];
    const float* mlp_b2  = (const float*)d_in[8];
    const float* gru_wih = (const float*)d_in[9];
    const float* gru_whh = (const float*)d_in[10];
    const float* gru_b   = (const float*)d_in[11];
    const float* gru_bn  = (const float*)d_in[12];
    const float* htl_w   = (const float*)d_in[13];
    const float* htl_b   = (const float*)d_in[14];
    const float* htb_w   = (const float*)d_in[15];
    const float* htb_b   = (const float*)d_in[16];
    const float* lti_w   = (const float*)d_in[17];
    const float* lti_b   = (const float*)d_in[18];
    const float* lth_w   = (const float*)d_in[19];
    const float* lth_b   = (const float*)d_in[20];

    static int attr_set = 0;
    if (!attr_set) {
        cudaFuncSetAttribute(solve_kernel,
                             cudaFuncAttributeMaxDynamicSharedMemorySize,
                             DYN_SMEM_BYTES);
        attr_set = 1;
    }

    prep_kernel<<<96, 256>>>(mlp_w0, mlp_w1, mlp_w2, gru_wih, gru_whh);
    solve_kernel<<<64, 512, DYN_SMEM_BYTES>>>(ts, ys, scale, mlp_b0, mlp_b1, mlp_b2,
                              gru_b, gru_bn, htl_w, htl_b, htb_w, htb_b,
                              lti_w, lti_b, lth_w, lth_b, (float*)d_out);
}

// round 14
// speedup vs baseline: 1.3874x; 1.0496x over previous
#include <cuda_runtime.h>
#include <cuda_bf16.h>

// Dims: B=64, T=64, D=32, H=128, W=256, L=64, K_SUB=2
typedef unsigned uint;
typedef unsigned long long u64t;

// ---------------- device scratch ----------------
__device__ float4 g_wihq[ 9 * 384];            // GRU input weights fp32 packed
__device__ float4 g_whhq[32 * 384];            // GRU hidden weights fp32 packed
// MLP weight tiles for ldmatrix: 16x16 bf16 tiles, row stride 48B (24 ushorts, 16 used)
__device__ unsigned short g_w0t[144 * 384];    // (256,144): 16 m-tiles x 9 k-tiles
__device__ unsigned short g_w2t[128 * 384];    // (128,256): 8 m-tiles x 16 k-tiles
// w1 A-fragments, per-thread: 16 k-tiles x 4 regs
__device__ uint4 g_w1f[512 * 16];

// RK coefficient tables (row s: coeffs for k0..k5; stage s uses k0..ks)
__constant__ float c_AT[6][6] = {
    {0.161f, 0, 0, 0, 0, 0},
    {(float)-0.008480655492356989, (float)0.335480655492357, 0, 0, 0, 0},
    {(float)2.8971530571054935, (float)-6.359448489975075, (float)4.3622954328695815, 0, 0, 0},
    {(float)5.325864828439257, (float)-11.748883564062828, (float)7.4955393428898365,
     (float)-0.09249506636175525, 0, 0},
    {(float)5.86145544294642, (float)-12.92096931784711, (float)8.159367898576159,
     (float)-0.071584973281401, (float)-0.028269050394068383, 0},
    {(float)0.09646076681806523, 0.01f, (float)0.4798896504144996,
     (float)1.379008574103742, (float)-3.290069515436081, (float)2.324710524099774}};
__constant__ float c_CC[5] = {0.161f, 0.327f, 0.9f, (float)0.9800255409045097, 1.0f};

__device__ __forceinline__ uint pk_bf2(float a, float b) {
    uint lo = (uint)__bfloat16_as_ushort(__float2bfloat16_rn(a));
    uint hi = (uint)__bfloat16_as_ushort(__float2bfloat16_rn(b));
    return (hi << 16) | lo;
}

// Activation-block permutation: within each 16-element (8-word) block, word order
// becomes (0,4),(1,5),(2,6),(3,7) so lane L's B-fragment pair (orig words L, L+4)
// is one aligned u64. perm16 maps element index -> permuted u16 index (bijective/block).
__host__ __device__ __forceinline__ int perm16(int e) {
    int wo = (e >> 1) & 7;
    int pw = ((wo & 3) << 1) | (wo >> 2);
    return ((e >> 4) << 4) | (pw << 1) | (e & 1);
}

__global__ void prep_kernel(const float* __restrict__ w0, const float* __restrict__ w1,
                            const float* __restrict__ w2, const float* __restrict__ wih,
                            const float* __restrict__ whh)
{
    int i0 = blockIdx.x * blockDim.x + threadIdx.x;
    int stride = gridDim.x * blockDim.x;

    // w0 tiles: tile = mt*9+kt; element (r,c) at tile*384 + r*24 + c (c<16 valid)
    // K index 0 -> col0 (t_hi), 1..128 -> h, 129 -> col0 again (t_lo), else 0
    for (int idx = i0; idx < 144 * 384; idx += stride) {
        int tile = idx / 384, e = idx % 384, r = e / 24, c = e % 24;
        float v = 0.f;
        if (c < 16) {
            int mt = tile / 9, kt = tile % 9;
            int R = 16 * mt + r, K = 16 * kt + c;
            if (K < 129)       v = w0[R * 129 + K];
            else if (K == 129) v = w0[R * 129];
        }
        g_w0t[idx] = __bfloat16_as_ushort(__float2bfloat16_rn(v));
    }
    // w2 tiles: tile = mt*16+kt
    for (int idx = i0; idx < 128 * 384; idx += stride) {
        int tile = idx / 384, e = idx % 384, r = e / 24, c = e % 24;
        float v = 0.f;
        if (c < 16) {
            int mt = tile >> 4, kt = tile & 15;
            int R = 16 * mt + r, K = 16 * kt + c;
            v = w2[R * 256 + K];
        }
        g_w2t[idx] = __bfloat16_as_ushort(__float2bfloat16_rn(v));
    }
    // w1 fragments: idx = t*64 + kt*4 + i
    for (int idx = i0; idx < 512 * 64; idx += stride) {
        int t = idx >> 6, rem = idx & 63, kt = rem >> 2, i = rem & 3;
        int wid = t >> 5, lane = t & 31, g = lane >> 2, tig = lane & 3;
        int R = 16 * wid + g + ((i & 1) ? 8 : 0);
        int K = 16 * kt + 2 * tig + ((i & 2) ? 8 : 0);
        ((uint*)g_w1f)[idx] = pk_bf2(w1[R * 256 + K], w1[R * 256 + K + 1]);
    }
    // GRU fp32 packs
    for (int idx = i0; idx < 9 * 384; idx += stride) {
        int k4 = idx / 384, j = idx % 384, k = 4 * k4;
        float4 v;
        v.x = (k + 0 < 33) ? wih[j * 33 + k + 0] : 0.f;
        v.y = (k + 1 < 33) ? wih[j * 33 + k + 1] : 0.f;
        v.z = (k + 2 < 33) ? wih[j * 33 + k + 2] : 0.f;
        v.w = (k + 3 < 33) ? wih[j * 33 + k + 3] : 0.f;
        g_wihq[idx] = v;
    }
    for (int idx = i0; idx < 32 * 384; idx += stride) {
        int k4 = idx / 384, j = idx % 384, k = 4 * k4;
        g_whhq[idx] = make_float4(whh[j * 128 + k], whh[j * 128 + k + 1],
                                  whh[j * 128 + k + 2], whh[j * 128 + k + 3]);
    }
}

// ---------------- helpers ----------------
__device__ __forceinline__ uint smem_u32(const void* p) {
    return (uint)__cvta_generic_to_shared(p);
}
__device__ __forceinline__ void ldsm4(uint& r0, uint& r1, uint& r2, uint& r3, uint addr) {
    asm volatile("ldmatrix.sync.aligned.m8n8.x4.shared.b16 {%0,%1,%2,%3}, [%4];"
                 : "=r"(r0), "=r"(r1), "=r"(r2), "=r"(r3) : "r"(addr));
}
__device__ __forceinline__ void mma16816(float* d,
                                         uint a0, uint a1, uint a2, uint a3,
                                         uint b0, uint b1) {
    asm volatile("mma.sync.aligned.m16n8k16.row.col.f32.bf16.bf16.f32 "
                 "{%0,%1,%2,%3}, {%4,%5,%6,%7}, {%8,%9}, {%0,%1,%2,%3};"
                 : "+f"(d[0]), "+f"(d[1]), "+f"(d[2]), "+f"(d[3])
                 : "r"(a0), "r"(a1), "r"(a2), "r"(a3), "r"(b0), "r"(b1));
}
__device__ __forceinline__ float tanh_fast(float x) {
    float y; asm("tanh.approx.f32 %0, %1;" : "=f"(y) : "f"(x)); return y;
}
__device__ __forceinline__ float softplus_fast(float x) {
    return fmaxf(x, 0.f) + __logf(1.f + __expf(-fabsf(x)));
}
__device__ __forceinline__ float sigmoid_fast(float x) { return 1.f / (1.f + __expf(-x)); }
__device__ __forceinline__ float sigmoidp(float x) { return 1.f / (1.f + expf(-x)); }
__device__ __forceinline__ unsigned short bf16u(float v) {
    return __bfloat16_as_ushort(__float2bfloat16_rn(v));
}
__device__ __forceinline__ float bf2f(unsigned short u) {
    return __uint_as_float(((uint)u) << 16);
}

// dynamic smem: phase 1 = whh fp32 (196608B); phase 2 = w0 tiles (110592B) + w2 tiles (98304B)
#define DYN_SMEM_BYTES 208896
#define W2_SMEM_OFF    110592

__global__ void __launch_bounds__(512, 1)
solve_kernel(const float* __restrict__ ts, const float* __restrict__ ys,
             const float* __restrict__ scale,
             const float* __restrict__ mlp_b0, const float* __restrict__ mlp_b1,
             const float* __restrict__ mlp_b2,
             const float* __restrict__ gru_b, const float* __restrict__ gru_bn,
             const float* __restrict__ htl_w, const float* __restrict__ htl_b,
             const float* __restrict__ htb_w, const float* __restrict__ htb_b,
             const float* __restrict__ lti_w, const float* __restrict__ lti_b,
             const float* __restrict__ lth_w, const float* __restrict__ lth_b,
             float* __restrict__ out)
{
    const int b   = blockIdx.x;
    const int tid = threadIdx.x;
    const int lane = tid & 31, wid = tid >> 5;
    const int g = lane >> 2, tig = lane & 3;

    extern __shared__ __align__(16) char s_dyn[];

    __shared__ __align__(16) float s_xg[36];
    __shared__ __align__(16) float s_hid[128];
    __shared__ float s_ih[384], s_hh[384];
    __shared__ __align__(16) float s_y[136];
    __shared__ float s_k[5][136];                        // k-stage history
    __shared__ __align__(16) unsigned short s_xb[144];   // PERMUTED bf16 activations
    __shared__ __align__(16) unsigned short s_a0b[256];  // PERMUTED
    __shared__ __align__(16) unsigned short s_a1b[256];  // PERMUTED
    __shared__ float s_z0[64];
    __shared__ float s_beta;

    const int OFF_H = 64 * 64 * 5;
    const int OFF_Z = OFF_H + 64 * 64 * 128;

    // ---- phase 1: whh into smem ----
    float4* s_whh = (float4*)s_dyn;
    for (int i = tid; i < 32 * 384; i += 512) s_whh[i] = g_whhq[i];

    const float gb  = (tid < 384) ? gru_b[tid]  : 0.f;
    const float gbn = (tid < 128) ? gru_bn[tid] : 0.f;

    if (tid < 128) s_hid[tid] = 0.f;
    if (tid >= 33 && tid < 36) s_xg[tid] = 0.f;
    __syncthreads();

    // ---------------- GRU over reversed sequence ----------------
    for (int step = 0; step < 64; ++step) {
        int r = 63 - step;
        if (tid == 0) s_xg[0] = ts[b * 64 + r];
        if (tid >= 1 && tid < 33) s_xg[tid] = ys[(b * 64 + r) * 32 + (tid - 1)];
        __syncthreads();

        if (tid < 384) {
            const float4* xg4 = (const float4*)s_xg;
            const float4* h4  = (const float4*)s_hid;
            int row = tid;
            float a0 = gb, a1 = 0.f;
            #pragma unroll
            for (int k = 0; k < 9; ++k) {
                float4 w = g_wihq[k * 384 + row];
                float4 x = xg4[k];
                a0 = fmaf(w.x, x.x, fmaf(w.z, x.z, a0));
                a1 = fmaf(w.y, x.y, fmaf(w.w, x.w, a1));
            }
            float c0 = 0.f, c1 = 0.f;
            #pragma unroll 8
            for (int k = 0; k < 32; ++k) {
                float4 w = s_whh[k * 384 + row];
                float4 x = h4[k];
                c0 = fmaf(w.x, x.x, fmaf(w.z, x.z, c0));
                c1 = fmaf(w.y, x.y, fmaf(w.w, x.w, c1));
            }
            s_ih[row] = a0 + a1;
            s_hh[row] = c0 + c1;
        }
        __syncthreads();
        if (tid < 128) {
            float rr = sigmoidp(s_ih[tid] + s_hh[tid]);
            float zz = sigmoidp(s_ih[128 + tid] + s_hh[128 + tid]);
            float nn = tanhf(s_ih[256 + tid] + rr * (s_hh[256 + tid] + gbn));
            s_hid[tid] = nn + zz * (s_hid[tid] - nn);
        }
        __syncthreads();
    }

    // ---------------- head ----------------
    if (tid < 64) {
        float acc = htl_b[tid];
        #pragma unroll 8
        for (int k = 0; k < 128; ++k) acc = fmaf(htl_w[tid * 128 + k], s_hid[k], acc);
        s_z0[tid] = acc;
        out[OFF_Z + b * 64 + tid] = acc;
    }
    __syncthreads();
    if (tid < 128) {
        float acc = lth_b[tid];
        #pragma unroll 8
        for (int k = 0; k < 64; ++k) acc = fmaf(lth_w[tid * 64 + k], s_z0[k], acc);
        s_y[5 + tid] = acc;
    }
    if (tid == 0) {
        float lg[5], mx = -1e30f;
        #pragma unroll
        for (int m = 0; m < 5; ++m) {
            float acc = lti_b[m];
            for (int k = 0; k < 64; ++k) acc = fmaf(lti_w[m * 64 + k], s_z0[k], acc);
            lg[m] = acc; mx = fmaxf(mx, acc);
        }
        float sum = 0.f;
        #pragma unroll
        for (int m = 0; m < 5; ++m) { float t = expf(lg[m] - mx); s_y[m] = t; sum += t; }
        #pragma unroll
        for (int m = 0; m < 5; ++m) s_y[m] /= sum;
    }
    __syncthreads();   // done with s_whh; s_y ready

    // ---- phase 2: MLP weight tiles into smem ----
    {
        uint4* dst0 = (uint4*)s_dyn;
        const uint4* src0 = (const uint4*)g_w0t;
        for (int i = tid; i < 144 * 384 / 8; i += 512) dst0[i] = src0[i];
        uint4* dst2 = (uint4*)(s_dyn + W2_SMEM_OFF);
        const uint4* src2 = (const uint4*)g_w2t;
        for (int i = tid; i < 128 * 384 / 8; i += 512) dst2[i] = src2[i];
    }

    // w1 fragments into registers
    uint4 w1f[16];
    #pragma unroll
    for (int j = 0; j < 16; ++j) w1f[j] = g_w1f[tid * 16 + j];

    // per-thread constants
    const int rowg = 16 * wid + g;
    const float b0lo = mlp_b0[rowg], b0hi = mlp_b0[rowg + 8];
    const float b1lo = mlp_b1[rowg], b1hi = mlp_b1[rowg + 8];
    float b2lo = 0.f, b2hi = 0.f;
    if (wid < 8) { b2lo = mlp_b2[rowg]; b2hi = mlp_b2[rowg + 8]; }
    const float scl = scale[0];

    // precomputed permuted write indices (loop-invariant per thread)
    const int iaw0 = perm16(rowg), iaw1 = perm16(rowg + 8);      // a0b/a1b epilogue
    const int ixA  = perm16(1 + rowg), ixB = perm16(9 + rowg);   // s_xb combine writes
    const int ixT0 = perm16(0), ixT1 = perm16(129);              // t slots (identity)

    float hw0 = 0.f, hw1 = 0.f, hw2 = 0.f, hw3 = 0.f, htbb = 0.f;
    int ibeta0 = 0, ibeta1 = 0, ibeta2 = 0, ibeta3 = 0;
    if (wid == 15) {
        hw0 = htb_w[lane]; hw1 = htb_w[lane + 32];
        hw2 = htb_w[lane + 64]; hw3 = htb_w[lane + 96];
        htbb = htb_b[0];
        ibeta0 = perm16(1 + lane);  ibeta1 = perm16(33 + lane);
        ibeta2 = perm16(65 + lane); ibeta3 = perm16(97 + lane);
    }

    const uint laneoff = (uint)((lane & 15) * 48 + (lane >> 4) * 16);
    const uint w0base = smem_u32(s_dyn) + (uint)(wid * 9 * 768) + laneoff;
    const uint w2base = smem_u32(s_dyn) + W2_SMEM_OFF + (uint)(wid * 16 * 768) + laneoff;

    // init s_xb (permuted) from initial state; t=0; y-base registers
    if (tid < 128) s_xb[perm16(1 + tid)] = bf16u(s_y[5 + tid]);
    if (tid == 256) { s_xb[ixT0] = 0; s_xb[ixT1] = 0; }
    if (tid >= 130 && tid < 144) s_xb[perm16(tid)] = 0;
    float ya = 0.f, yb = 0.f;
    if (wid < 8 && tig == 0) { ya = s_y[5 + rowg]; yb = s_y[13 + rowg]; }
    // SEIAR base + stage state in warp 15 lane 0 registers
    float yS0 = 0, yS1 = 0, yS2 = 0, yS3 = 0, yS4 = 0;   // y-base
    float tS0 = 0, tS1 = 0, tS2 = 0, tS3 = 0, tS4 = 0;   // stage state
    if (wid == 15 && lane == 0) {
        yS0 = s_y[0]; yS1 = s_y[1]; yS2 = s_y[2]; yS3 = s_y[3]; yS4 = s_y[4];
        tS0 = yS0; tS1 = yS1; tS2 = yS2; tS3 = yS3; tS4 = yS4;
    }
    __syncthreads();

    // ---------------- tsit5: 6 stages, 3 barriers each ----------------
    auto tsit5 = [&](float tt, float h, float t_after) {
        #pragma unroll 1
        for (int s = 0; s < 6; ++s) {
            // --- phase A: layer 0 (+ beta on warp 15); 2 acc sets; LDS.64 B loads ---
            {
                const u64t* x64 = (const u64t*)s_xb;
                float d[4] = {}, f[4] = {};
                #pragma unroll
                for (int kt = 0; kt < 9; ++kt) {
                    uint a0, a1, a2, a3;
                    ldsm4(a0, a1, a2, a3, w0base + (uint)(kt * 768));
                    uint p0 = 0, p1 = 0;
                    if (lane < 4) {
                        u64t v = x64[4 * kt + lane];
                        p0 = (uint)v; p1 = (uint)(v >> 32);
                    }
                    if (kt & 1) mma16816(f, a0, a1, a2, a3, p0, p1);
                    else        mma16816(d, a0, a1, a2, a3, p0, p1);
                }
                if (wid == 15) {
                    float p = fmaf(hw0, bf2f(s_xb[ibeta0]),
                              fmaf(hw1, bf2f(s_xb[ibeta1]),
                              fmaf(hw2, bf2f(s_xb[ibeta2]),
                                   hw3 * bf2f(s_xb[ibeta3]))));
                    #pragma unroll
                    for (int o = 16; o > 0; o >>= 1) p += __shfl_xor_sync(0xffffffffu, p, o);
                    if (lane == 0) s_beta = sigmoid_fast(0.01f * (p + htbb));
                }
                if (tig == 0) {
                    s_a0b[iaw0] = bf16u(softplus_fast(d[0] + f[0] + b0lo));
                    s_a0b[iaw1] = bf16u(softplus_fast(d[2] + f[2] + b0hi));
                }
            }
            __syncthreads();

            // --- phase B: layer 1 (A fragments in registers); 2 acc sets; LDS.64 B loads ---
            {
                const u64t* y64 = (const u64t*)s_a0b;
                float d[4] = {}, f[4] = {};
                #pragma unroll
                for (int kt = 0; kt < 16; ++kt) {
                    uint p0 = 0, p1 = 0;
                    if (lane < 4) {
                        u64t v = y64[4 * kt + lane];
                        p0 = (uint)v; p1 = (uint)(v >> 32);
                    }
                    if (kt & 1) mma16816(f, w1f[kt].x, w1f[kt].y, w1f[kt].z, w1f[kt].w, p0, p1);
                    else        mma16816(d, w1f[kt].x, w1f[kt].y, w1f[kt].z, w1f[kt].w, p0, p1);
                }
                if (tig == 0) {
                    s_a1b[iaw0] = bf16u(softplus_fast(d[0] + f[0] + b1lo));
                    s_a1b[iaw1] = bf16u(softplus_fast(d[2] + f[2] + b1hi));
                }
            }
            __syncthreads();

            // --- phase C: layer 2 (full-K, warps 0-7, 2 acc sets) fused with RK combine ---
            if (wid < 8) {
                const u64t* y64 = (const u64t*)s_a1b;
                float d[4] = {}, f[4] = {};
                #pragma unroll
                for (int kt = 0; kt < 16; ++kt) {
                    uint a0, a1, a2, a3;
                    ldsm4(a0, a1, a2, a3, w2base + (uint)(kt * 768));
                    uint p0 = 0, p1 = 0;
                    if (lane < 4) {
                        u64t v = y64[4 * kt + lane];
                        p0 = (uint)v; p1 = (uint)(v >> 32);
                    }
                    if (kt & 1) mma16816(f, a0, a1, a2, a3, p0, p1);
                    else        mma16816(d, a0, a1, a2, a3, p0, p1);
                }
                if (tig == 0) {
                    float kA = scl * (0.1f * tanh_fast(1e-4f * (d[0] + f[0] + b2lo)));
                    float kB = scl * (0.1f * tanh_fast(1e-4f * (d[2] + f[2] + b2hi)));
                    float sA = c_AT[s][s] * kA, sB = c_AT[s][s] * kB;
                    #pragma unroll 1
                    for (int j = 0; j < s; ++j) {
                        sA += c_AT[s][j] * s_k[j][5 + rowg];
                        sB += c_AT[s][j] * s_k[j][13 + rowg];
                    }
                    if (s < 5) { s_k[s][5 + rowg] = kA; s_k[s][13 + rowg] = kB; }
                    float vA = ya + h * sA, vB = yb + h * sB;
                    s_xb[ixA] = bf16u(vA);
                    s_xb[ixB] = bf16u(vB);
                    if (s == 5) { ya = vA; yb = vB; s_y[5 + rowg] = vA; s_y[13 + rowg] = vB; }
                }
            } else if (wid == 15 && lane == 0) {
                // SEIAR: all 5 components serially in one lane (no warp coupling)
                float S = tS0, E = tS1, I = tS2, A_ = tS3;
                float LL = 0.5f * I + A_;
                float bSL = s_beta * S * LL;
                float k0v = -bSL;
                float k1v = bSL - 0.526f * E;
                float k2v = fmaf((float)(0.667 * 0.526), E, -(0.244f * I));
                float k3v = fmaf((float)((1.0 - 0.667) * 0.526), E, -(0.244f * A_));
                float k4v = fmaf((float)(0.98 * 0.244), I, 0.244f * A_);
                float s0 = c_AT[s][s] * k0v, s1 = c_AT[s][s] * k1v, s2 = c_AT[s][s] * k2v;
                float s3 = c_AT[s][s] * k3v, s4 = c_AT[s][s] * k4v;
                #pragma unroll 1
                for (int j = 0; j < s; ++j) {
                    float c = c_AT[s][j];
                    s0 += c * s_k[j][0]; s1 += c * s_k[j][1]; s2 += c * s_k[j][2];
                    s3 += c * s_k[j][3]; s4 += c * s_k[j][4];
                }
                if (s < 5) {
                    s_k[s][0] = k0v; s_k[s][1] = k1v; s_k[s][2] = k2v;
                    s_k[s][3] = k3v; s_k[s][4] = k4v;
                }
                tS0 = yS0 + h * s0; tS1 = yS1 + h * s1; tS2 = yS2 + h * s2;
                tS3 = yS3 + h * s3; tS4 = yS4 + h * s4;
                if (s == 5) {
                    yS0 = tS0; yS1 = tS1; yS2 = tS2; yS3 = tS3; yS4 = tS4;
                    s_y[0] = tS0; s_y[1] = tS1; s_y[2] = tS2; s_y[3] = tS3; s_y[4] = tS4;
                }
                // t-slot for next vf eval
                float tn = (s < 5) ? tt + c_CC[s] * h : t_after;
                unsigned short u = bf16u(tn);
                s_xb[ixT0] = u;
                s_xb[ixT1] = bf16u(tn - bf2f(u));
            }
            __syncthreads();
        }
    };

    float t0v = 0.f;
    for (int st = 0; st < 64; ++st) {
        float tn = ts[b * 64 + st];
        float dt = (tn - t0v) * 0.5f;    // K_SUB = 2
        tsit5(t0v,      dt, t0v + dt);
        tsit5(t0v + dt, dt, tn);
        t0v = tn;
        if (tid < 5)   out[(b * 64 + st) * 5 + tid] = s_y[tid];
        if (tid < 128) out[OFF_H + (b * 64 + st) * 128 + tid] = s_y[5 + tid];
    }
}

extern "C" void kernel_launch(void* const* d_in, const int* in_sizes, int n_in,
                              void* d_out, int out_size) {
    const float* ts      = (const float*)d_in[0];
    const float* ys      = (const float*)d_in[1];
    const float* scale   = (const float*)d_in[2];
    const float* mlp_w0  = (const float*)d_in[3];
    const float* mlp_b0  = (const float*)d_in[4];
    const float* mlp_w1  = (const float*)d_in[5];
    const float* mlp_b1  = (const float*)d_in[6];
    const float* mlp_w2  = (const float*)d_in[7];
    const float* mlp_b2  = (const float*)d_in[8];
    const float* gru_wih = (const float*)d_in[9];
    const float* gru_whh = (const float*)d_in[10];
    const float* gru_b   = (const float*)d_in[11];
    const float* gru_bn  = (const float*)d_in[12];
    const float* htl_w   = (const float*)d_in[13];
    const float* htl_b   = (const float*)d_in[14];
    const float* htb_w   = (const float*)d_in[15];
    const float* htb_b   = (const float*)d_in[16];
    const float* lti_w   = (const float*)d_in[17];
    const float* lti_b   = (const float*)d_in[18];
    const float* lth_w   = (const float*)d_in[19];
    const float* lth_b   = (const float*)d_in[20];

    static int attr_set = 0;
    if (!attr_set) {
        cudaFuncSetAttribute(solve_kernel,
                             cudaFuncAttributeMaxDynamicSharedMemorySize,
                             DYN_SMEM_BYTES);
        attr_set = 1;
    }

    prep_kernel<<<96, 256>>>(mlp_w0, mlp_w1, mlp_w2, gru_wih, gru_whh);
    solve_kernel<<<64, 512, DYN_SMEM_BYTES>>>(ts, ys, scale, mlp_b0, mlp_b1, mlp_b2,
                              gru_b, gru_bn, htl_w, htl_b, htb_w, htb_b,
                              lti_w, lti_b, lth_w, lth_b, (float*)d_out);
}